// round 2
// baseline (speedup 1.0000x reference)
#include <cuda_runtime.h>

#define DEV __device__ __forceinline__
#define BIG 1.0e30f

__constant__ float c_mean[3] = {0.485f, 0.456f, 0.406f};
__constant__ float c_std[3]  = {0.229f, 0.224f, 0.225f};

DEV void cas(float &a, float &b) { float t = fminf(a, b); b = fmaxf(a, b); a = t; }

// Batcher odd-even merge of two sorted runs: x[0..P-1] and x[P..N-1], N <= 2P.
// (Quotient condition of the classic network is vacuous when N <= 2P.)
template<int N, int P, int K>
DEV void oem_pass(float* x) {
    if constexpr (K == P) {
        #pragma unroll
        for (int i = 0; i + P < N; ++i) cas(x[i], x[i + P]);
    } else {
        #pragma unroll
        for (int j = K; j + K < N; j += 2 * K) {
            #pragma unroll
            for (int i = 0; i < K; ++i)
                if (i + j + K < N) cas(x[i + j], x[i + j + K]);
        }
    }
    if constexpr (K > 1) oem_pass<N, P, K / 2>(x);
}

// 16-CAS sort of 7 (Batcher sort-8 with slot7=+inf, sentinel CAS removed).
DEV void sort7(float* x) {
    cas(x[0], x[1]); cas(x[2], x[3]); cas(x[0], x[2]); cas(x[1], x[3]); cas(x[1], x[2]);
    cas(x[4], x[5]); cas(x[4], x[6]); cas(x[5], x[6]);
    cas(x[0], x[4]); cas(x[1], x[5]); cas(x[2], x[6]);
    cas(x[2], x[4]); cas(x[3], x[5]);
    cas(x[1], x[2]); cas(x[3], x[4]); cas(x[5], x[6]);
}

// merge two sorted 7s -> sorted 14 in out[0..13]
DEV void merge77(const float* a, const float* b, float* out) {
    float x[15];
    #pragma unroll
    for (int i = 0; i < 7; ++i) x[i] = a[i];
    x[7] = BIG;
    #pragma unroll
    for (int i = 0; i < 7; ++i) x[8 + i] = b[i];
    oem_pass<15, 8, 8>(x);
    #pragma unroll
    for (int i = 0; i < 14; ++i) out[i] = x[i];
}

// S[0..27] = sorted merge of two sorted 14s (S has room for 30)
DEV void build_S(const float* A, const float* B, float* S) {
    #pragma unroll
    for (int i = 0; i < 14; ++i) S[i] = A[i];
    S[14] = BIG; S[15] = BIG;
    #pragma unroll
    for (int i = 0; i < 14; ++i) S[16 + i] = B[i];
    oem_pass<30, 16, 16>(S);
}

// E = sorted merge of sorted 14 (C) and sorted 7 (g); return rank-25 of S(28) U E(21):
// kth = min_i max(S[i-1], E[25-i-1]), i in [4,25]; i=25 term is S[24].
DEV float final_select(const float* S, const float* C, const float* g) {
    float x[23];
    #pragma unroll
    for (int i = 0; i < 14; ++i) x[i] = C[i];
    x[14] = BIG; x[15] = BIG;
    #pragma unroll
    for (int i = 0; i < 7; ++i) x[16 + i] = g[i];
    oem_pass<23, 16, 16>(x);             // E = x[0..20]
    float m = S[24];
    #pragma unroll
    for (int i = 4; i <= 24; ++i) m = fminf(m, fmaxf(S[i - 1], x[24 - i]));
    return m;
}

// One CTA = one output row of one (batch,channel) plane; 128 threads x 4 px.
__global__ __launch_bounds__(128) void median7_kernel(const float* __restrict__ img,
                                                      float* __restrict__ out) {
    const int y     = blockIdx.x;        // 0..511
    const int plane = blockIdx.y;        // 0..23
    const int ch    = plane % 3;
    const float mean = c_mean[ch];
    const float sd   = c_std[ch];

    __shared__ float srow[7][518];
    const float* src = img + (size_t)plane * 262144;

    #pragma unroll
    for (int r = 0; r < 7; ++r) {
        int gy = y + r - 3;
        gy = (gy < 0) ? -gy : ((gy > 511) ? 1022 - gy : gy);
        const float* rp = src + gy * 512;
        for (int c = threadIdx.x; c < 518; c += 128) {
            int gx = c - 3;
            gx = (gx < 0) ? -gx : ((gx > 511) ? 1022 - gx : gx);
            float v = fmaf(rp[gx], sd, mean);
            srow[r][c] = fminf(fmaxf(v, 0.0f), 1.0f);
        }
    }
    __syncthreads();

    const int x0 = threadIdx.x * 4;      // first output pixel

    // Column pairs P0..P4 over smem cols x0+t (global x0-3+t), plus lone columns.
    float P0[14], P1[14], P2[14], P3[14], P4[14];
    float lone1[7], lone3[7], lone6[7], lone8[7];
    {
        float ca[7], cb[7];
        #pragma unroll
        for (int d = 0; d < 7; ++d) { ca[d] = srow[d][x0 + 0]; cb[d] = srow[d][x0 + 1]; }
        sort7(ca); sort7(cb);
        #pragma unroll
        for (int d = 0; d < 7; ++d) lone1[d] = cb[d];
        merge77(ca, cb, P0);
        #pragma unroll
        for (int d = 0; d < 7; ++d) { ca[d] = srow[d][x0 + 2]; cb[d] = srow[d][x0 + 3]; }
        sort7(ca); sort7(cb);
        #pragma unroll
        for (int d = 0; d < 7; ++d) lone3[d] = cb[d];
        merge77(ca, cb, P1);
        #pragma unroll
        for (int d = 0; d < 7; ++d) { ca[d] = srow[d][x0 + 4]; cb[d] = srow[d][x0 + 5]; }
        sort7(ca); sort7(cb);
        merge77(ca, cb, P2);
        #pragma unroll
        for (int d = 0; d < 7; ++d) { ca[d] = srow[d][x0 + 6]; cb[d] = srow[d][x0 + 7]; }
        sort7(ca); sort7(cb);
        #pragma unroll
        for (int d = 0; d < 7; ++d) lone6[d] = ca[d];
        merge77(ca, cb, P3);
        #pragma unroll
        for (int d = 0; d < 7; ++d) { ca[d] = srow[d][x0 + 8]; cb[d] = srow[d][x0 + 9]; }
        sort7(ca); sort7(cb);
        #pragma unroll
        for (int d = 0; d < 7; ++d) lone8[d] = ca[d];
        merge77(ca, cb, P4);
    }

    float S[30];
    build_S(P0, P1, S);
    float m0 = final_select(S, P2, lone6);   // px x0:   P0,P1,P2 + col(x0+3)
    build_S(P1, P2, S);
    float m1 = final_select(S, P3, lone1);   // px x0+1: P1,P2,P3 + col(x0-2)
    float m2 = final_select(S, P3, lone8);   // px x0+2: P1,P2,P3 + col(x0+5)
    build_S(P2, P3, S);
    float m3 = final_select(S, P4, lone3);   // px x0+3: P2,P3,P4 + col(x0)

    const float inv = 1.0f / sd;
    float4 o;
    o.x = (m0 - mean) * inv;
    o.y = (m1 - mean) * inv;
    o.z = (m2 - mean) * inv;
    o.w = (m3 - mean) * inv;
    *reinterpret_cast<float4*>(out + (size_t)plane * 262144 + y * 512 + x0) = o;
}

extern "C" void kernel_launch(void* const* d_in, const int* in_sizes, int n_in,
                              void* d_out, int out_size) {
    const float* img  = (const float*)d_in[0];
    const float* mask = (const float*)d_in[1];
    float* out = (float*)d_out;
    const int img_elems  = in_sizes[0];   // 8*3*512*512
    const int mask_elems = in_sizes[1];   // 8*1*512*512

    dim3 grid(512, 24);
    median7_kernel<<<grid, 128>>>(img, out);
    cudaMemcpyAsync(out + img_elems, mask, (size_t)mask_elems * sizeof(float),
                    cudaMemcpyDeviceToDevice);
}

// round 4
// speedup vs baseline: 1.3550x; 1.3550x over previous
#include <cuda_runtime.h>

#define DEV __device__ __forceinline__
#define BIG 1.0e30f

__constant__ float c_mean[3] = {0.485f, 0.456f, 0.406f};
__constant__ float c_std[3]  = {0.229f, 0.224f, 0.225f};

DEV void cas(float &a, float &b) { float t = fminf(a, b); b = fmaxf(a, b); a = t; }

// Batcher odd-even merge of sorted runs x[0..P-1], x[P..N-1]; valid for N <= 2P.
template<int N, int P, int K>
DEV void oem_pass(float* x) {
    if constexpr (K == P) {
        #pragma unroll
        for (int i = 0; i + P < N; ++i) cas(x[i], x[i + P]);
    } else {
        #pragma unroll
        for (int j = K; j + K < N; j += 2 * K) {
            #pragma unroll
            for (int i = 0; i < K; ++i)
                if (i + j + K < N) cas(x[i + j], x[i + j + K]);
        }
    }
    if constexpr (K > 1) oem_pass<N, P, K / 2>(x);
}

// 16-CAS sort of 7.
DEV void sort7(float* x) {
    cas(x[0], x[1]); cas(x[2], x[3]); cas(x[0], x[2]); cas(x[1], x[3]); cas(x[1], x[2]);
    cas(x[4], x[5]); cas(x[4], x[6]); cas(x[5], x[6]);
    cas(x[0], x[4]); cas(x[1], x[5]); cas(x[2], x[6]);
    cas(x[2], x[4]); cas(x[3], x[5]);
    cas(x[1], x[2]); cas(x[3], x[4]); cas(x[5], x[6]);
}

// S[0..27] = sorted merge of two sorted 14s (S has room for 30).
DEV void build_S(const float* A, const float* B, float* S) {
    #pragma unroll
    for (int i = 0; i < 14; ++i) S[i] = A[i];
    S[14] = BIG; S[15] = BIG;
    #pragma unroll
    for (int i = 0; i < 14; ++i) S[16 + i] = B[i];
    oem_pass<30, 16, 16>(S);
}

// E = merge(sorted 14 C, sorted 7 g); return rank-25 of S(28) U E(21):
// med = min_{i=4..25} max(S[i-1], E[24-i]); i=25 term is S[24].
DEV float final_select(const float* S, const float* C, const float* g) {
    float x[23];
    #pragma unroll
    for (int i = 0; i < 14; ++i) x[i] = C[i];
    x[14] = BIG; x[15] = BIG;
    #pragma unroll
    for (int i = 0; i < 7; ++i) x[16 + i] = g[i];
    oem_pass<23, 16, 16>(x);             // E = x[0..20]
    float m = S[24];
    #pragma unroll
    for (int i = 4; i <= 24; ++i) m = fminf(m, fmaxf(S[i - 1], x[24 - i]));
    return m;
}

// One CTA = one output row of one (b,c) plane; 128 threads x 4 px.
// Phase 1 cooperatively sorts all 518 columns (in place in srow) and merges all
// 259 aligned column pairs into transposed pairbuf; phase 2: per-pixel select.
__global__ __launch_bounds__(128, 5) void median7_kernel(const float* __restrict__ img,
                                                         float* __restrict__ out) {
    const int y     = blockIdx.x;        // 0..511
    const int plane = blockIdx.y;        // 0..23
    const int ch    = plane % 3;
    const float mean = c_mean[ch];
    const float sd   = c_std[ch];

    __shared__ float srow[7][518];       // rows -> sorted columns (in place)
    __shared__ float pairbuf[14][260];   // transposed: element i of pair m at [i][m]

    const float* src = img + (size_t)plane * 262144;

    #pragma unroll
    for (int r = 0; r < 7; ++r) {
        int gy = y + r - 3;
        gy = (gy < 0) ? -gy : ((gy > 511) ? 1022 - gy : gy);
        const float* rp = src + gy * 512;
        for (int c = threadIdx.x; c < 518; c += 128) {
            int gx = c - 3;
            gx = (gx < 0) ? -gx : ((gx > 511) ? 1022 - gx : gx);
            float v = fmaf(rp[gx], sd, mean);
            srow[r][c] = fminf(fmaxf(v, 0.0f), 1.0f);
        }
    }
    __syncthreads();

    // Phase 1: task m owns columns 2m, 2m+1 exclusively (m < 259).
    for (int m = threadIdx.x; m < 259; m += 128) {
        float x[15];
        float cb[7];
        #pragma unroll
        for (int d = 0; d < 7; ++d) { x[d] = srow[d][2 * m]; cb[d] = srow[d][2 * m + 1]; }
        sort7(x); sort7(cb);
        #pragma unroll
        for (int d = 0; d < 7; ++d) { srow[d][2 * m] = x[d]; srow[d][2 * m + 1] = cb[d]; }
        x[7] = BIG;
        #pragma unroll
        for (int d = 0; d < 7; ++d) x[8 + d] = cb[d];
        oem_pass<15, 8, 8>(x);           // x[0..13] sorted
        #pragma unroll
        for (int i = 0; i < 14; ++i) pairbuf[i][m] = x[i];
    }
    __syncthreads();

    const int t  = threadIdx.x;
    const int x0 = 4 * t;                // smem col of px0's leftmost window col

    float P2[14], P3[14];                // long-lived pairs
    float S[30];

    // S_A = S(pair 2t+1, pair 2t+2): serves px0, px1, px2.
    {
        float P1[14];
        #pragma unroll
        for (int i = 0; i < 14; ++i) P1[i] = pairbuf[i][2 * t + 1];
        #pragma unroll
        for (int i = 0; i < 14; ++i) P2[i] = pairbuf[i][2 * t + 2];
        build_S(P1, P2, S);
    }

    float m0, m1, m2, m3;
    {   // px0: E(pair 2t, lone col x0+6)
        float P0[14], g[7];
        #pragma unroll
        for (int i = 0; i < 14; ++i) P0[i] = pairbuf[i][2 * t];
        #pragma unroll
        for (int d = 0; d < 7; ++d) g[d] = srow[d][x0 + 6];
        m0 = final_select(S, P0, g);
    }
    {   // px1: E(pair 2t+3, lone col x0+1); px2: E(pair 2t+3, lone col x0+8)
        #pragma unroll
        for (int i = 0; i < 14; ++i) P3[i] = pairbuf[i][2 * t + 3];
        float g[7];
        #pragma unroll
        for (int d = 0; d < 7; ++d) g[d] = srow[d][x0 + 1];
        m1 = final_select(S, P3, g);
        #pragma unroll
        for (int d = 0; d < 7; ++d) g[d] = srow[d][x0 + 8];
        m2 = final_select(S, P3, g);
    }
    {   // px3: S_B = S(pair 2t+3, pair 2t+4); E(pair 2t+2, lone col x0+3)
        float P4[14], g[7];
        #pragma unroll
        for (int i = 0; i < 14; ++i) P4[i] = pairbuf[i][2 * t + 4];
        build_S(P3, P4, S);
        #pragma unroll
        for (int d = 0; d < 7; ++d) g[d] = srow[d][x0 + 3];
        m3 = final_select(S, P2, g);
    }

    const float inv = 1.0f / sd;
    float4 o;
    o.x = (m0 - mean) * inv;
    o.y = (m1 - mean) * inv;
    o.z = (m2 - mean) * inv;
    o.w = (m3 - mean) * inv;
    *reinterpret_cast<float4*>(out + (size_t)plane * 262144 + y * 512 + x0) = o;
}

extern "C" void kernel_launch(void* const* d_in, const int* in_sizes, int n_in,
                              void* d_out, int out_size) {
    const float* img  = (const float*)d_in[0];
    const float* mask = (const float*)d_in[1];
    float* out = (float*)d_out;
    const int img_elems  = in_sizes[0];
    const int mask_elems = in_sizes[1];

    dim3 grid(512, 24);
    median7_kernel<<<grid, 128>>>(img, out);
    cudaMemcpyAsync(out + img_elems, mask, (size_t)mask_elems * sizeof(float),
                    cudaMemcpyDeviceToDevice);
}

// round 5
// speedup vs baseline: 1.4986x; 1.1060x over previous
#include <cuda_runtime.h>

#define DEV __device__ __forceinline__
#define BIG 1.0e30f

__constant__ float c_mean[3] = {0.485f, 0.456f, 0.406f};
__constant__ float c_std[3]  = {0.229f, 0.224f, 0.225f};

DEV void cas(float &a, float &b) { float t = fminf(a, b); b = fmaxf(a, b); a = t; }

// Batcher odd-even merge of sorted runs x[0..P-1], x[P..N-1]; valid for N <= 2P.
template<int N, int P, int K>
DEV void oem_pass(float* x) {
    if constexpr (K == P) {
        #pragma unroll
        for (int i = 0; i + P < N; ++i) cas(x[i], x[i + P]);
    } else {
        #pragma unroll
        for (int j = K; j + K < N; j += 2 * K) {
            #pragma unroll
            for (int i = 0; i < K; ++i)
                if (i + j + K < N) cas(x[i + j], x[i + j + K]);
        }
    }
    if constexpr (K > 1) oem_pass<N, P, K / 2>(x);
}

// 16-CAS sort of 7.
DEV void sort7(float* x) {
    cas(x[0], x[1]); cas(x[2], x[3]); cas(x[0], x[2]); cas(x[1], x[3]); cas(x[1], x[2]);
    cas(x[4], x[5]); cas(x[4], x[6]); cas(x[5], x[6]);
    cas(x[0], x[4]); cas(x[1], x[5]); cas(x[2], x[6]);
    cas(x[2], x[4]); cas(x[3], x[5]);
    cas(x[1], x[2]); cas(x[3], x[4]); cas(x[5], x[6]);
}

// S[0..27] = sorted merge of two sorted 14s (S has room for 30).
DEV void build_S(const float* A, const float* B, float* S) {
    #pragma unroll
    for (int i = 0; i < 14; ++i) S[i] = A[i];
    S[14] = BIG; S[15] = BIG;
    #pragma unroll
    for (int i = 0; i < 14; ++i) S[16 + i] = B[i];
    oem_pass<30, 16, 16>(S);
}

// E = merge(sorted 14 C, sorted 7 g); rank-25 of S(28) U E(21):
// med = min_{i=4..25} max(S[i-1], E[24-i]); i=25 term is S[24]. Tree-reduced min.
DEV float final_select(const float* S, const float* C, const float* g) {
    float x[23];
    #pragma unroll
    for (int i = 0; i < 14; ++i) x[i] = C[i];
    x[14] = BIG; x[15] = BIG;
    #pragma unroll
    for (int i = 0; i < 7; ++i) x[16 + i] = g[i];
    oem_pass<23, 16, 16>(x);             // E = x[0..20]
    float t[22];
    t[0] = S[24];
    #pragma unroll
    for (int i = 4; i <= 24; ++i) t[i - 3] = fmaxf(S[i - 1], x[24 - i]);
    #pragma unroll
    for (int st = 1; st < 22; st *= 2) {
        #pragma unroll
        for (int i = 0; i + st < 22; i += 2 * st) t[i] = fminf(t[i], t[i + st]);
    }
    return t[0];
}

// One CTA = one output row of one (b,c) plane; 256 threads x 2 px.
// Phase 1 cooperatively sorts all 518 columns (in place) and merges all 259
// aligned column pairs into transposed pairbuf; phase 2: per-pixel select.
// Adjacent pixels 2t,2t+1 share all three aligned pairs -> one build_S serves both.
__global__ __launch_bounds__(256, 3) void median7_kernel(const float* __restrict__ img,
                                                         float* __restrict__ out) {
    const int y     = blockIdx.x;        // 0..511
    const int plane = blockIdx.y;        // 0..23
    const int ch    = plane % 3;
    const float mean = c_mean[ch];
    const float sd   = c_std[ch];

    __shared__ float srow[7][518];       // rows -> sorted columns (in place)
    __shared__ float pairbuf[14][260];   // transposed: element i of pair m at [i][m]

    const float* src = img + (size_t)plane * 262144;

    #pragma unroll
    for (int r = 0; r < 7; ++r) {
        int gy = y + r - 3;
        gy = (gy < 0) ? -gy : ((gy > 511) ? 1022 - gy : gy);
        const float* rp = src + gy * 512;
        for (int c = threadIdx.x; c < 518; c += 256) {
            int gx = c - 3;
            gx = (gx < 0) ? -gx : ((gx > 511) ? 1022 - gx : gx);
            float v = fmaf(rp[gx], sd, mean);
            srow[r][c] = fminf(fmaxf(v, 0.0f), 1.0f);
        }
    }
    __syncthreads();

    // Phase 1: task m owns smem columns 2m, 2m+1 exclusively (m < 259).
    for (int m = threadIdx.x; m < 259; m += 256) {
        float x[15];
        float cb[7];
        #pragma unroll
        for (int d = 0; d < 7; ++d) { x[d] = srow[d][2 * m]; cb[d] = srow[d][2 * m + 1]; }
        sort7(x); sort7(cb);
        #pragma unroll
        for (int d = 0; d < 7; ++d) { srow[d][2 * m] = x[d]; srow[d][2 * m + 1] = cb[d]; }
        x[7] = BIG;
        #pragma unroll
        for (int d = 0; d < 7; ++d) x[8 + d] = cb[d];
        oem_pass<15, 8, 8>(x);           // x[0..13] sorted
        #pragma unroll
        for (int i = 0; i < 14; ++i) pairbuf[i][m] = x[i];
    }
    __syncthreads();

    const int t = threadIdx.x;           // px0 global col = 2t; smem center col 2t+3

    // S = merge(pair t+1, pair t+2): shared by px0 (window smem 2t..2t+6)
    // and px1 (window smem 2t+1..2t+7).
    float S[30];
    {
        float P1[14], P2[14];
        #pragma unroll
        for (int i = 0; i < 14; ++i) P1[i] = pairbuf[i][t + 1];
        #pragma unroll
        for (int i = 0; i < 14; ++i) P2[i] = pairbuf[i][t + 2];
        build_S(P1, P2, S);
    }

    float m0, m1;
    {   // px0: E(pair t, lone smem col 2t+6)
        float C[14], g[7];
        #pragma unroll
        for (int i = 0; i < 14; ++i) C[i] = pairbuf[i][t];
        #pragma unroll
        for (int d = 0; d < 7; ++d) g[d] = srow[d][2 * t + 6];
        m0 = final_select(S, C, g);
    }
    {   // px1: E(pair t+3, lone smem col 2t+1)
        float C[14], g[7];
        #pragma unroll
        for (int i = 0; i < 14; ++i) C[i] = pairbuf[i][t + 3];
        #pragma unroll
        for (int d = 0; d < 7; ++d) g[d] = srow[d][2 * t + 1];
        m1 = final_select(S, C, g);
    }

    const float inv = 1.0f / sd;
    float2 o;
    o.x = (m0 - mean) * inv;
    o.y = (m1 - mean) * inv;
    *reinterpret_cast<float2*>(out + (size_t)plane * 262144 + y * 512 + 2 * t) = o;
}

extern "C" void kernel_launch(void* const* d_in, const int* in_sizes, int n_in,
                              void* d_out, int out_size) {
    const float* img  = (const float*)d_in[0];
    const float* mask = (const float*)d_in[1];
    float* out = (float*)d_out;
    const int img_elems  = in_sizes[0];
    const int mask_elems = in_sizes[1];

    dim3 grid(512, 24);
    median7_kernel<<<grid, 256>>>(img, out);
    cudaMemcpyAsync(out + img_elems, mask, (size_t)mask_elems * sizeof(float),
                    cudaMemcpyDeviceToDevice);
}